// round 16
// baseline (speedup 1.0000x reference)
#include <cuda_runtime.h>
#include <stdint.h>
#include <math.h>

// ---------------------------------------------------------------------------
// ProposalLayer: decode -> clip -> min-size filter -> top-12000 -> NMS(0.7)
//                -> first 2000 kept boxes (zero padded)
// R15: launch-floor attack: 8 -> 5 kernels. select fused into decode's last
//      block (1024-thr blocks), binscatter+rank2 fused behind a 64-block
//      resident spin barrier, tail fused into resolve (union'd smem).
// ---------------------------------------------------------------------------

#define NMAX    147456
#define NPRE    12000
#define NPOST   2000
#define CAP     16384
#define NMS_T   0.7f
#define TOPPAD  12032
#define B1      4096         // stage-1 NMS coverage (64 chunks)
#define BINS    8192

typedef unsigned long long ull;

// ------------------------- scratch (device globals) ------------------------
__device__ unsigned int g_keys[NMAX];
__device__ float4       g_boxes[NMAX];
__device__ int          g_hist1[65536];
__device__ int          g_hist2[65536];
__device__ unsigned int g_kthKey;        // 0/1 => gather all valid
__device__ int          g_binShift;
__device__ int          g_candCount;
__device__ int          g_decodeDone;
__device__ int          g_gatherDone;
__device__ int          g_binDone;
__device__ ull          g_cand[CAP];
__device__ int          g_binCnt[BINS];
__device__ int          g_binFill[BINS];
__device__ int          g_binS[BINS];    // # candidates in strictly higher bins
__device__ ull          g_binArr[CAP];
__device__ float4       g_topBox[TOPPAD];
__device__ float        g_topArea[TOPPAD];
__device__ int          g_validTop;
__device__ ull          g_maskT[(size_t)B1 * 64];   // column-major, stage-1
__device__ ull          g_diag[B1];

__device__ __forceinline__ int shift_from(unsigned kth, int maxB) {
    ull range = ((ull)(maxB + 1) << 16) - (ull)kth;
    if (maxB < 0 || range == 0ull) range = 1ull;
    int blen = 64 - __clzll(range | 1ull);
    return (blen > 13) ? (blen - 13) : 0;
}

// ---------- K1: decode + clip + key + hist1; LAST BLOCK: select ------------
__global__ void __launch_bounds__(1024) k_decode(
        const float4* __restrict__ anc4, const float4* __restrict__ off4,
        const float* __restrict__ sc,
        const int* __restrict__ ph, const int* __restrict__ pw,
        const int* __restrict__ ps, int n) {
    int tid = threadIdx.x;
    int i = blockIdx.x * 1024 + tid;

    if (i < n) {
        float H = (float)ph[0];
        float W = (float)pw[0];
        float minsz = __fmul_rn(16.0f, (float)ps[0]);

        float4 a = anc4[i];
        float4 o = off4[i];

        float ah  = __fsub_rn(a.z, a.x);
        float aw  = __fsub_rn(a.w, a.y);
        float acy = __fadd_rn(a.x, __fmul_rn(0.5f, ah));
        float acx = __fadd_rn(a.y, __fmul_rn(0.5f, aw));
        float cy  = __fadd_rn(__fmul_rn(o.x, ah), acy);
        float cx  = __fadd_rn(__fmul_rn(o.y, aw), acx);
        float h   = __fmul_rn(expf(o.z), ah);
        float w   = __fmul_rn(expf(o.w), aw);

        float y1 = __fsub_rn(cy, __fmul_rn(0.5f, h));
        float x1 = __fsub_rn(cx, __fmul_rn(0.5f, w));
        float y2 = __fadd_rn(cy, __fmul_rn(0.5f, h));
        float x2 = __fadd_rn(cx, __fmul_rn(0.5f, w));

        y1 = fminf(fmaxf(y1, 0.0f), H);
        x1 = fminf(fmaxf(x1, 0.0f), W);
        y2 = fminf(fmaxf(y2, 0.0f), H);
        x2 = fminf(fmaxf(x2, 0.0f), W);

        float rh = __fsub_rn(y2, y1);
        float rw = __fsub_rn(x2, x1);
        bool valid = (rh >= minsz) && (rw >= minsz);

        unsigned key = 0u;
        if (valid) {
            unsigned u = __float_as_uint(sc[i]);
            key = (u & 0x80000000u) ? ~u : (u | 0x80000000u);
            if (key == 0u) key = 1u;
        }
        g_keys[i]  = key;
        g_boxes[i] = make_float4(y1, x1, y2, x2);
        if (key) atomicAdd(&g_hist1[key >> 16], 1);
    }

    // ---- completion: last block runs threshold select ----
    __threadfence();
    __syncthreads();
    __shared__ int sLast;
    if (tid == 0)
        sLast = (atomicAdd(&g_decodeDone, 1) == (int)gridDim.x - 1);
    __syncthreads();
    if (!sLast) return;

    __shared__ int part[1024];
    __shared__ int sNeed2, sT, sC1, sMaxB;
    int t = tid;
    if (t == 0) sNeed2 = 0;

    const int4* h4 = (const int4*)g_hist1;
    int s = 0;
    int hi = -1;
#pragma unroll
    for (int k = 0; k < 16; k++) {
        int4 v = __ldcg(h4 + t * 16 + k);
        s += v.x + v.y + v.z + v.w;
        int b4 = t * 64 + k * 4;
        if (v.w) hi = b4 + 3;
        else if (v.z) hi = b4 + 2;
        else if (v.y) hi = b4 + 1;
        else if (v.x) hi = b4;
    }
    part[t] = hi;
    __syncthreads();
    for (int o = 512; o >= 1; o >>= 1) {
        if (t < o) { int v = part[t + o]; if (v > part[t]) part[t] = v; }
        __syncthreads();
    }
    if (t == 0) sMaxB = part[0];
    __syncthreads();

    part[t] = s;
    __syncthreads();
    for (int o = 1; o < 1024; o <<= 1) {
        int v = part[t] + ((t + o < 1024) ? part[t + o] : 0);
        __syncthreads();
        part[t] = v;
        __syncthreads();
    }
    int Sincl = part[t], Sexcl = Sincl - s;
    if (t == 0 && part[0] < NPRE)
        g_binShift = shift_from(1u, sMaxB);   // gather-all-valid fallback
    if (Sexcl < NPRE && Sincl >= NPRE) {
        int base = t * 64, cum = Sexcl;
        for (int b = base + 63; b >= base; b--) {
            int hb = __ldcg(&g_hist1[b]);
            cum += hb;
            if (cum >= NPRE) {
                if (cum <= CAP) {
                    unsigned kk = ((unsigned)b) << 16;
                    if (kk == 0u) kk = 1u;
                    g_kthKey = kk;
                    g_binShift = shift_from(kk, sMaxB);
                } else {
                    sNeed2 = 1; sT = b; sC1 = cum - hb;
                }
                break;
            }
        }
    }
    __syncthreads();
    if (!sNeed2) return;

    // ---- rare: exact 32-bit refinement within bucket sT ----
    for (int k = t; k < 65536; k += 1024) g_hist2[k] = 0;
    __syncthreads();
    unsigned T = (unsigned)sT;
    for (int j = t; j < n; j += 1024) {
        unsigned key = g_keys[j];
        if (key && (key >> 16) == T) atomicAdd(&g_hist2[key & 0xFFFFu], 1);
    }
    __syncthreads();
    int C1 = sC1;
    const int4* h42 = (const int4*)g_hist2;
    s = 0;
#pragma unroll
    for (int k = 0; k < 16; k++) {
        int4 v = __ldcg(h42 + t * 16 + k);
        s += v.x + v.y + v.z + v.w;
    }
    part[t] = s;
    __syncthreads();
    for (int o = 1; o < 1024; o <<= 1) {
        int v = part[t] + ((t + o < 1024) ? part[t + o] : 0);
        __syncthreads();
        part[t] = v;
        __syncthreads();
    }
    Sincl = part[t]; Sexcl = Sincl - s;
    if (C1 + Sexcl < NPRE && C1 + Sincl >= NPRE) {
        int base = t * 64, cum = C1 + Sexcl;
        for (int b = base + 63; b >= base; b--) {
            cum += __ldcg(&g_hist2[b]);
            if (cum >= NPRE) {
                unsigned kk = (T << 16) | (unsigned)b;
                g_kthKey = kk;
                g_binShift = shift_from(kk, sMaxB);
                break;
            }
        }
    }
}

// ------ K2: gather + bin histogram; LAST BLOCK: vectorized suffix scan -----
__global__ void __launch_bounds__(256) k_gather(int n) {
    int i = blockIdx.x * blockDim.x + threadIdx.x;
    unsigned kth = g_kthKey;
    int shift = g_binShift;

    unsigned key = (i < n) ? g_keys[i] : 0u;
    bool want = key && key >= kth;
    unsigned bal = __ballot_sync(0xffffffffu, want);
    if (bal) {
        int lane = threadIdx.x & 31;
        int leader = __ffs(bal) - 1;
        int base = 0;
        if (lane == leader) base = atomicAdd(&g_candCount, __popc(bal));
        base = __shfl_sync(0xffffffffu, base, leader);
        if (want) {
            int p = base + __popc(bal & ((1u << lane) - 1u));
            if (p < CAP) {
                // composite: score key desc, then index asc (top_k tie-break)
                g_cand[p] = ((ull)key << 32) | (ull)(0xFFFFFFFFu - (unsigned)i);
                atomicAdd(&g_binCnt[(key - kth) >> shift], 1);
            }
        }
    }

    __threadfence();
    __syncthreads();
    __shared__ int sLast;
    if (threadIdx.x == 0)
        sLast = (atomicAdd(&g_gatherDone, 1) == (int)gridDim.x - 1);
    __syncthreads();
    if (!sLast) return;

    __shared__ int part[256];
    int t = threadIdx.x;
    const int4* bc4 = (const int4*)g_binCnt;
    int4 v[8];
    int s = 0;
#pragma unroll
    for (int k = 0; k < 8; k++) {
        v[k] = __ldcg(bc4 + t * 8 + k);
        s += v[k].x + v[k].y + v[k].z + v[k].w;
    }
    part[t] = s;
    __syncthreads();
    for (int o = 1; o < 256; o <<= 1) {
        int p2 = part[t] + ((t + o < 256) ? part[t + o] : 0);
        __syncthreads();
        part[t] = p2;
        __syncthreads();
    }
    int acc = part[t] - s;
    int4* bs4 = (int4*)g_binS;
#pragma unroll
    for (int k = 7; k >= 0; k--) {
        int4 w;
        w.w = acc; acc += v[k].w;
        w.z = acc; acc += v[k].z;
        w.y = acc; acc += v[k].y;
        w.x = acc; acc += v[k].x;
        bs4[t * 8 + k] = w;
    }
    if (t == 0) {
        int m = g_candCount; if (m > CAP) m = CAP;
        g_validTop = (m < NPRE) ? m : NPRE;
    }
}

// --- K3: CSR scatter + resident spin barrier + exact intra-bin rank --------
__global__ void __launch_bounds__(256) k_binrank() {
    int m = g_candCount; if (m > CAP) m = CAP;
    int p = blockIdx.x * 256 + threadIdx.x;
    unsigned kth = g_kthKey;
    int shift = g_binShift;

    ull c = 0ull;
    unsigned bin = 0;
    int lo = 0;
    bool active = (p < m);
    if (active) {
        c = g_cand[p];
        bin = ((unsigned)(c >> 32) - kth) >> shift;
        lo = g_binS[bin];
        int pos = lo + atomicAdd(&g_binFill[bin], 1);
        g_binArr[pos] = c;
    }

    // resident spin barrier across 64 blocks (all co-resident)
    __threadfence();
    __syncthreads();
    if (threadIdx.x == 0) {
        atomicAdd(&g_binDone, 1);
        while (__ldcg(&g_binDone) < (int)gridDim.x) __nanosleep(64);
    }
    __syncthreads();

    if (!active) return;
    int cnt = __ldg(&g_binCnt[bin]);
    int r = lo;
    for (int q = lo; q < lo + cnt; q++)
        r += (__ldcg(&g_binArr[q]) > c) ? 1 : 0;   // composites unique => exact
    if (r < NPRE) {
        unsigned idx = 0xFFFFFFFFu - (unsigned)c;
        float4 b = g_boxes[idx];
        g_topBox[r]  = b;
        g_topArea[r] = __fmul_rn(__fsub_rn(b.z, b.x), __fsub_rn(b.w, b.y));
    }
}

// ----------- IoU decision (reference-exact fp32: fdiv then compare) --------
__device__ __forceinline__ bool iou_gt(float4 a, float aa, float4 b, float ab) {
    float ty = fmaxf(a.x, b.x);
    float tx = fmaxf(a.y, b.y);
    float by = fminf(a.z, b.z);
    float bx = fminf(a.w, b.w);
    float hh = fmaxf(__fsub_rn(by, ty), 0.0f);
    float ww = fmaxf(__fsub_rn(bx, tx), 0.0f);
    float inter = __fmul_rn(hh, ww);
    float uni = __fsub_rn(__fadd_rn(aa, ab), inter);
    float iou = __fdiv_rn(inter, fmaxf(uni, 1e-9f));
    return iou > NMS_T;
}

// ---- K4: stage-1 suppression mask, COLUMN-major words + diag row words ----
__global__ void k_maskT() {
    int cb = blockIdx.x;
    int rb = blockIdx.y;
    if (cb > rb) return;

    __shared__ float4 rB[64];
    __shared__ float  rA[64];
    int t = threadIdx.x;
    rB[t] = g_topBox[rb * 64 + t];
    rA[t] = g_topArea[rb * 64 + t];
    __syncthreads();

    bool isDiag = (rb == cb);
    int colg = cb * 64 + t;
    float4 cbox = isDiag ? rB[t] : g_topBox[colg];
    float  ca   = isDiag ? rA[t] : g_topArea[colg];

    ull word = 0ull;
    int r0 = isDiag ? t + 1 : 0;
    for (int r = r0; r < 64; r++)
        if (iou_gt(cbox, ca, rB[r], rA[r])) word |= (1ull << r);
    g_maskT[(size_t)colg * 64 + rb] = word;

    if (isDiag) {
        ull dw = 0ull;
        float4 rbox = rB[t];
        float  ra = rA[t];
        for (int j = 0; j < t; j++)
            if (iou_gt(rbox, ra, rB[j], rA[j])) dw |= (1ull << j);
        g_diag[rb * 64 + t] = dw;
    }
}

// ------ K5: resolve (frontier greedy + MLP supB updates) + fused tail ------
__global__ void __launch_bounds__(512, 1) k_resolve(float* __restrict__ out) {
    __shared__ ull supB[64];
    __shared__ ull keptMask[64];
    __shared__ ull sDiag[2][64];
    __shared__ int keptList[64];
    __shared__ int sNK, sKept, sStop;
    __shared__ int wordBase[64];
    __shared__ float4 kb[NPOST];
    __shared__ float  ka[NPOST];
    __shared__ __align__(16) unsigned char uBuf[4096];   // supPart | tail scratch
    ull (*supPart)[64] = (ull (*)[64])uBuf;

    int tid = threadIdx.x, lane = tid & 31, warp = tid >> 5;   // 16 warps
    int vt = g_validTop;
    int end = (vt < B1) ? vt : B1;

    if (tid < 64) { supB[tid] = 0ull; keptMask[tid] = 0ull; }
    if (tid == 0) { sKept = 0; sNK = 0; sStop = (end <= 0) ? 1 : 0; }
    if (tid < 64) sDiag[0][tid] = (tid < end) ? __ldg(&g_diag[tid]) : 0ull;
    __syncthreads();

    if (!sStop) {
        int keptR = 0;
        int pb = 0;
        for (int base = 0; base < end; base += 64, pb ^= 1) {
            int cw = base >> 6;
            int cn = end - base; if (cn > 64) cn = 64;
            int nbase = base + 64;

            if (warp == 0) {
                ull sup = supB[cw];
                ull cand = ~sup;
                if (cn < 64) cand &= (1ull << cn) - 1ull;
                ull rowLo = sDiag[pb][lane];
                ull rowHi = sDiag[pb][lane + 32];
                ull U = cand, K = 0ull;
                while (U) {   // frontier rounds == sequential greedy
                    bool flo = ((U >> lane) & 1ull) && ((rowLo & U) == 0ull);
                    bool fhi = ((U >> (lane + 32)) & 1ull) && ((rowHi & U) == 0ull);
                    ull F = (ull)__ballot_sync(0xffffffffu, flo)
                          | ((ull)__ballot_sync(0xffffffffu, fhi) << 32);
                    K |= F;
                    bool qlo = (rowLo & F) != 0ull;
                    bool qhi = (rowHi & F) != 0ull;
                    ull S = (ull)__ballot_sync(0xffffffffu, qlo)
                          | ((ull)__ballot_sync(0xffffffffu, qhi) << 32);
                    U &= ~(F | S | K);
                }
                int c = __popcll(K);
                int room = NPOST - keptR;
                while (c > room) { K &= ~(1ull << (63 - __clzll(K))); c--; }
                keptR += c;
                bool bLo = (K >> lane) & 1ull;
                bool bHi = (K >> (lane + 32)) & 1ull;
                int pLo = __popcll(K & ((1ull << lane) - 1ull));
                int pHi = __popcll(K & ((1ull << (lane + 32)) - 1ull));
                if (bLo) keptList[pLo] = lane;
                if (bHi) keptList[pHi] = lane + 32;
                if (lane == 0) {
                    keptMask[cw] = K;
                    sNK = c;
                    sKept = keptR;
                    sStop = (keptR >= NPOST) ? 1 : 0;
                }
            } else if (warp == 1 && nbase < end) {
                sDiag[pb ^ 1][lane] =
                    (nbase + lane < end) ? __ldg(&g_diag[nbase + lane]) : 0ull;
                sDiag[pb ^ 1][lane + 32] =
                    (nbase + lane + 32 < end) ? __ldg(&g_diag[nbase + lane + 32]) : 0ull;
            }
            __syncthreads();

            int nK = sNK;
            if (sStop || nbase >= end) break;

            if (nK) {
                int g = tid >> 6, w = tid & 63;
                int lo = (nK * g) >> 3;
                int hi = (nK * (g + 1)) >> 3;
                ull a0 = 0ull, a1 = 0ull;
                int c2 = lo;
                for (; c2 + 2 <= hi; c2 += 2) {
                    a0 |= __ldg(&g_maskT[(size_t)(base + keptList[c2])     * 64 + w]);
                    a1 |= __ldg(&g_maskT[(size_t)(base + keptList[c2 + 1]) * 64 + w]);
                }
                if (c2 < hi)
                    a0 |= __ldg(&g_maskT[(size_t)(base + keptList[c2]) * 64 + w]);
                supPart[g][w] = a0 | a1;
                __syncthreads();
                if (tid < 64)
                    supB[tid] |= supPart[0][tid] | supPart[1][tid] | supPart[2][tid]
                               | supPart[3][tid] | supPart[4][tid] | supPart[5][tid]
                               | supPart[6][tid] | supPart[7][tid];
                __syncthreads();
            }
        }
    }
    __syncthreads();

    int kept = sKept;

    // ---- epilogue: prefix popcounts + parallel output writes + zero fill --
    if (warp == 0) {
        int carry = 0;
        for (int g = 0; g < 64; g += 32) {
            int ww = g + lane;
            int v = __popcll(keptMask[ww]);
            int incl = v;
#pragma unroll
            for (int o = 1; o < 32; o <<= 1) {
                int t2 = __shfl_up_sync(0xffffffffu, incl, o);
                if (lane >= o) incl += t2;
            }
            wordBase[ww] = carry + incl - v;
            carry += __shfl_sync(0xffffffffu, incl, 31);
        }
    }
    __syncthreads();
    for (int p = tid; p < 64 * 64; p += 512) {
        int w = p >> 6, b = p & 63;
        ull km = keptMask[w];
        if ((km >> b) & 1ull) {
            int pos = wordBase[w] + __popcll(km & ((1ull << b) - 1ull));
            ((float4*)out)[pos] = g_topBox[w * 64 + b];
        }
    }
    for (int p = kept * 4 + tid; p < NPOST * 4; p += 512) out[p] = 0.0f;

    // ---- cleanup for next graph replay (self-cleaning pipeline) ----
    if (tid == 0) {
        g_candCount  = 0;
        g_decodeDone = 0;
        g_gatherDone = 0;
        g_binDone    = 0;
        g_kthKey     = 1u;
    }
    {
        int4* h = (int4*)g_hist1;
        for (int k = tid; k < 16384; k += 512) h[k] = make_int4(0, 0, 0, 0);
        int4* bc = (int4*)g_binCnt;
        for (int k = tid; k < BINS / 4; k += 512) bc[k] = make_int4(0, 0, 0, 0);
        int4* bf = (int4*)g_binFill;
        for (int k = tid; k < BINS / 4; k += 512) bf[k] = make_int4(0, 0, 0, 0);
    }
    __syncthreads();

    // ================= fused tail (rare): ranks >= B1 ======================
    if (kept >= NPOST || vt <= B1) return;

    // tail scratch overlays uBuf (supPart no longer used)
    float4* cb   = (float4*)(uBuf);             // 64 * 16 = 1024 B
    float*  caA  = (float*)(uBuf + 1024);       // 64 * 4  = 256 B
    ull*    lmask = (ull*)(uBuf + 1280);        // 64 * 8  = 512 B
    int*    supf  = (int*)(uBuf + 1792);        // 64 * 4  = 256 B
    __shared__ ull sKeepLocal;
    __shared__ int sKept2;

    // build kept box list (in kept order) from smem keptMask/wordBase
    for (int p = tid; p < 64 * 64; p += 512) {
        int w = p >> 6, b = p & 63;
        ull km = keptMask[w];
        if ((km >> b) & 1ull) {
            int pos = wordBase[w] + __popcll(km & ((1ull << b) - 1ull));
            kb[pos] = g_topBox[w * 64 + b];
            ka[pos] = g_topArea[w * 64 + b];
        }
    }
    __syncthreads();

    for (int base = B1; base < vt && kept < NPOST; base += 64) {
        int cn = vt - base; if (cn > 64) cn = 64;

        if (tid < 64) {
            supf[tid]  = 0;
            lmask[tid] = 0ull;
            if (tid < cn) {
                cb[tid]  = g_topBox[base + tid];
                caA[tid] = g_topArea[base + tid];
            }
        }
        __syncthreads();

        for (int i = warp; i < cn; i += 16) {
            float4 bi = cb[i];
            float  ai = caA[i];
            bool any = false;
            for (int j = lane; j < kept; j += 32)
                if (iou_gt(bi, ai, kb[j], ka[j])) { any = true; break; }
            bool w = __any_sync(0xffffffffu, any);
            if (w && lane == 0) supf[i] = 1;
        }
        for (int p = tid; p < 64 * 64; p += 512) {
            int i = p >> 6, j = p & 63;
            if (i < cn && j < i)
                if (iou_gt(cb[i], caA[i], cb[j], caA[j]))
                    atomicOr(&lmask[i], 1ull << j);
        }
        __syncthreads();

        if (tid == 0) {
            ull kl = 0ull;
            int kc = kept;
            for (int i = 0; i < cn && kc < NPOST; i++) {
                if (!supf[i] && !(lmask[i] & kl)) { kl |= 1ull << i; kc++; }
            }
            sKeepLocal = kl; sKept2 = kc;
        }
        __syncthreads();

        ull kl = sKeepLocal;
        if (tid < cn && ((kl >> tid) & 1ull)) {
            int pos = kept + __popcll(kl & ((1ull << tid) - 1ull));
            kb[pos] = cb[tid];
            ka[pos] = caA[tid];
            ((float4*)out)[pos] = cb[tid];
        }
        __syncthreads();
        kept = sKept2;
        __syncthreads();
    }
}

// ------------------------------- launcher ----------------------------------
extern "C" void kernel_launch(void* const* d_in, const int* in_sizes, int n_in,
                              void* d_out, int out_size) {
    const float* anchors = (const float*)d_in[0];
    const float* offsets = (const float*)d_in[1];
    const float* scores  = (const float*)d_in[2];
    const int*   ph      = (const int*)d_in[3];
    const int*   pw      = (const int*)d_in[4];
    const int*   ps      = (const int*)d_in[5];
    float* out = (float*)d_out;

    int n = in_sizes[2];
    if (n > NMAX) n = NMAX;

    k_decode<<<(n + 1023) / 1024, 1024>>>((const float4*)anchors,
                                          (const float4*)offsets,
                                          scores, ph, pw, ps, n);
    k_gather<<<(n + 255) / 256, 256>>>(n);
    k_binrank<<<CAP / 256, 256>>>();
    k_maskT<<<dim3(64, 64), 64>>>();
    k_resolve<<<1, 512>>>(out);
}

// round 17
// speedup vs baseline: 1.1394x; 1.1394x over previous
#include <cuda_runtime.h>
#include <stdint.h>
#include <math.h>

// ---------------------------------------------------------------------------
// ProposalLayer: decode -> clip -> min-size filter -> top-12000 -> NMS(0.7)
//                -> first 2000 kept boxes (zero padded)
// R16: maskT rebuilt: 2080 triangular blocks x 256 thr (4 row-groups/tile) +
//      screened EXACT IoU compare (fp32 FMA fast path, fdiv only in a
//      provably-safe +/-25% band around the threshold). Resolve supB update
//      4-way unrolled. Skeleton otherwise identical to R15 (5 launches).
// ---------------------------------------------------------------------------

#define NMAX    147456
#define NPRE    12000
#define NPOST   2000
#define CAP     16384
#define NMS_T   0.7f
#define TOPPAD  12032
#define B1      4096         // stage-1 NMS coverage (64 chunks)
#define BINS    8192
#define NTILES1 2080         // 64*65/2 triangular tiles

typedef unsigned long long ull;

// ------------------------- scratch (device globals) ------------------------
__device__ unsigned int g_keys[NMAX];
__device__ float4       g_boxes[NMAX];
__device__ int          g_hist1[65536];
__device__ int          g_hist2[65536];
__device__ unsigned int g_kthKey;        // 0/1 => gather all valid
__device__ int          g_binShift;
__device__ int          g_candCount;
__device__ int          g_decodeDone;
__device__ int          g_gatherDone;
__device__ int          g_binDone;
__device__ ull          g_cand[CAP];
__device__ int          g_binCnt[BINS];
__device__ int          g_binFill[BINS];
__device__ int          g_binS[BINS];    // # candidates in strictly higher bins
__device__ ull          g_binArr[CAP];
__device__ float4       g_topBox[TOPPAD];
__device__ float        g_topArea[TOPPAD];
__device__ int          g_validTop;
__device__ ull          g_maskT[(size_t)B1 * 64];   // column-major, stage-1
__device__ ull          g_diag[B1];

__device__ __forceinline__ int shift_from(unsigned kth, int maxB) {
    ull range = ((ull)(maxB + 1) << 16) - (ull)kth;
    if (maxB < 0 || range == 0ull) range = 1ull;
    int blen = 64 - __clzll(range | 1ull);
    return (blen > 13) ? (blen - 13) : 0;
}

// ---------- K1: decode + clip + key + hist1; LAST BLOCK: select ------------
__global__ void __launch_bounds__(1024) k_decode(
        const float4* __restrict__ anc4, const float4* __restrict__ off4,
        const float* __restrict__ sc,
        const int* __restrict__ ph, const int* __restrict__ pw,
        const int* __restrict__ ps, int n) {
    int tid = threadIdx.x;
    int i = blockIdx.x * 1024 + tid;

    if (i < n) {
        float H = (float)ph[0];
        float W = (float)pw[0];
        float minsz = __fmul_rn(16.0f, (float)ps[0]);

        float4 a = anc4[i];
        float4 o = off4[i];

        float ah  = __fsub_rn(a.z, a.x);
        float aw  = __fsub_rn(a.w, a.y);
        float acy = __fadd_rn(a.x, __fmul_rn(0.5f, ah));
        float acx = __fadd_rn(a.y, __fmul_rn(0.5f, aw));
        float cy  = __fadd_rn(__fmul_rn(o.x, ah), acy);
        float cx  = __fadd_rn(__fmul_rn(o.y, aw), acx);
        float h   = __fmul_rn(expf(o.z), ah);
        float w   = __fmul_rn(expf(o.w), aw);

        float y1 = __fsub_rn(cy, __fmul_rn(0.5f, h));
        float x1 = __fsub_rn(cx, __fmul_rn(0.5f, w));
        float y2 = __fadd_rn(cy, __fmul_rn(0.5f, h));
        float x2 = __fadd_rn(cx, __fmul_rn(0.5f, w));

        y1 = fminf(fmaxf(y1, 0.0f), H);
        x1 = fminf(fmaxf(x1, 0.0f), W);
        y2 = fminf(fmaxf(y2, 0.0f), H);
        x2 = fminf(fmaxf(x2, 0.0f), W);

        float rh = __fsub_rn(y2, y1);
        float rw = __fsub_rn(x2, x1);
        bool valid = (rh >= minsz) && (rw >= minsz);

        unsigned key = 0u;
        if (valid) {
            unsigned u = __float_as_uint(sc[i]);
            key = (u & 0x80000000u) ? ~u : (u | 0x80000000u);
            if (key == 0u) key = 1u;
        }
        g_keys[i]  = key;
        g_boxes[i] = make_float4(y1, x1, y2, x2);
        if (key) atomicAdd(&g_hist1[key >> 16], 1);
    }

    // ---- completion: last block runs threshold select ----
    __threadfence();
    __syncthreads();
    __shared__ int sLast;
    if (tid == 0)
        sLast = (atomicAdd(&g_decodeDone, 1) == (int)gridDim.x - 1);
    __syncthreads();
    if (!sLast) return;

    __shared__ int part[1024];
    __shared__ int sNeed2, sT, sC1, sMaxB;
    int t = tid;
    if (t == 0) sNeed2 = 0;

    const int4* h4 = (const int4*)g_hist1;
    int s = 0;
    int hi = -1;
#pragma unroll
    for (int k = 0; k < 16; k++) {
        int4 v = __ldcg(h4 + t * 16 + k);
        s += v.x + v.y + v.z + v.w;
        int b4 = t * 64 + k * 4;
        if (v.w) hi = b4 + 3;
        else if (v.z) hi = b4 + 2;
        else if (v.y) hi = b4 + 1;
        else if (v.x) hi = b4;
    }
    part[t] = hi;
    __syncthreads();
    for (int o = 512; o >= 1; o >>= 1) {
        if (t < o) { int v = part[t + o]; if (v > part[t]) part[t] = v; }
        __syncthreads();
    }
    if (t == 0) sMaxB = part[0];
    __syncthreads();

    part[t] = s;
    __syncthreads();
    for (int o = 1; o < 1024; o <<= 1) {
        int v = part[t] + ((t + o < 1024) ? part[t + o] : 0);
        __syncthreads();
        part[t] = v;
        __syncthreads();
    }
    int Sincl = part[t], Sexcl = Sincl - s;
    if (t == 0 && part[0] < NPRE)
        g_binShift = shift_from(1u, sMaxB);   // gather-all-valid fallback
    if (Sexcl < NPRE && Sincl >= NPRE) {
        int base = t * 64, cum = Sexcl;
        for (int b = base + 63; b >= base; b--) {
            int hb = __ldcg(&g_hist1[b]);
            cum += hb;
            if (cum >= NPRE) {
                if (cum <= CAP) {
                    unsigned kk = ((unsigned)b) << 16;
                    if (kk == 0u) kk = 1u;
                    g_kthKey = kk;
                    g_binShift = shift_from(kk, sMaxB);
                } else {
                    sNeed2 = 1; sT = b; sC1 = cum - hb;
                }
                break;
            }
        }
    }
    __syncthreads();
    if (!sNeed2) return;

    // ---- rare: exact 32-bit refinement within bucket sT ----
    for (int k = t; k < 65536; k += 1024) g_hist2[k] = 0;
    __syncthreads();
    unsigned T = (unsigned)sT;
    for (int j = t; j < n; j += 1024) {
        unsigned key = g_keys[j];
        if (key && (key >> 16) == T) atomicAdd(&g_hist2[key & 0xFFFFu], 1);
    }
    __syncthreads();
    int C1 = sC1;
    const int4* h42 = (const int4*)g_hist2;
    s = 0;
#pragma unroll
    for (int k = 0; k < 16; k++) {
        int4 v = __ldcg(h42 + t * 16 + k);
        s += v.x + v.y + v.z + v.w;
    }
    part[t] = s;
    __syncthreads();
    for (int o = 1; o < 1024; o <<= 1) {
        int v = part[t] + ((t + o < 1024) ? part[t + o] : 0);
        __syncthreads();
        part[t] = v;
        __syncthreads();
    }
    Sincl = part[t]; Sexcl = Sincl - s;
    if (C1 + Sexcl < NPRE && C1 + Sincl >= NPRE) {
        int base = t * 64, cum = C1 + Sexcl;
        for (int b = base + 63; b >= base; b--) {
            cum += __ldcg(&g_hist2[b]);
            if (cum >= NPRE) {
                unsigned kk = (T << 16) | (unsigned)b;
                g_kthKey = kk;
                g_binShift = shift_from(kk, sMaxB);
                break;
            }
        }
    }
}

// ------ K2: gather + bin histogram; LAST BLOCK: vectorized suffix scan -----
__global__ void __launch_bounds__(256) k_gather(int n) {
    int i = blockIdx.x * blockDim.x + threadIdx.x;
    unsigned kth = g_kthKey;
    int shift = g_binShift;

    unsigned key = (i < n) ? g_keys[i] : 0u;
    bool want = key && key >= kth;
    unsigned bal = __ballot_sync(0xffffffffu, want);
    if (bal) {
        int lane = threadIdx.x & 31;
        int leader = __ffs(bal) - 1;
        int base = 0;
        if (lane == leader) base = atomicAdd(&g_candCount, __popc(bal));
        base = __shfl_sync(0xffffffffu, base, leader);
        if (want) {
            int p = base + __popc(bal & ((1u << lane) - 1u));
            if (p < CAP) {
                // composite: score key desc, then index asc (top_k tie-break)
                g_cand[p] = ((ull)key << 32) | (ull)(0xFFFFFFFFu - (unsigned)i);
                atomicAdd(&g_binCnt[(key - kth) >> shift], 1);
            }
        }
    }

    __threadfence();
    __syncthreads();
    __shared__ int sLast;
    if (threadIdx.x == 0)
        sLast = (atomicAdd(&g_gatherDone, 1) == (int)gridDim.x - 1);
    __syncthreads();
    if (!sLast) return;

    __shared__ int part[256];
    int t = threadIdx.x;
    const int4* bc4 = (const int4*)g_binCnt;
    int4 v[8];
    int s = 0;
#pragma unroll
    for (int k = 0; k < 8; k++) {
        v[k] = __ldcg(bc4 + t * 8 + k);
        s += v[k].x + v[k].y + v[k].z + v[k].w;
    }
    part[t] = s;
    __syncthreads();
    for (int o = 1; o < 256; o <<= 1) {
        int p2 = part[t] + ((t + o < 256) ? part[t + o] : 0);
        __syncthreads();
        part[t] = p2;
        __syncthreads();
    }
    int acc = part[t] - s;
    int4* bs4 = (int4*)g_binS;
#pragma unroll
    for (int k = 7; k >= 0; k--) {
        int4 w;
        w.w = acc; acc += v[k].w;
        w.z = acc; acc += v[k].z;
        w.y = acc; acc += v[k].y;
        w.x = acc; acc += v[k].x;
        bs4[t * 8 + k] = w;
    }
    if (t == 0) {
        int m = g_candCount; if (m > CAP) m = CAP;
        g_validTop = (m < NPRE) ? m : NPRE;
    }
}

// --- K3: CSR scatter + resident spin barrier + exact intra-bin rank --------
__global__ void __launch_bounds__(256) k_binrank() {
    int m = g_candCount; if (m > CAP) m = CAP;
    int p = blockIdx.x * 256 + threadIdx.x;
    unsigned kth = g_kthKey;
    int shift = g_binShift;

    ull c = 0ull;
    unsigned bin = 0;
    int lo = 0;
    bool active = (p < m);
    if (active) {
        c = g_cand[p];
        bin = ((unsigned)(c >> 32) - kth) >> shift;
        lo = g_binS[bin];
        int pos = lo + atomicAdd(&g_binFill[bin], 1);
        g_binArr[pos] = c;
    }

    // resident spin barrier across 64 blocks (all co-resident)
    __threadfence();
    __syncthreads();
    if (threadIdx.x == 0) {
        atomicAdd(&g_binDone, 1);
        while (__ldcg(&g_binDone) < (int)gridDim.x) __nanosleep(64);
    }
    __syncthreads();

    if (!active) return;
    int cnt = __ldg(&g_binCnt[bin]);
    int r = lo;
    for (int q = lo; q < lo + cnt; q++)
        r += (__ldcg(&g_binArr[q]) > c) ? 1 : 0;   // composites unique => exact
    if (r < NPRE) {
        unsigned idx = 0xFFFFFFFFu - (unsigned)c;
        float4 b = g_boxes[idx];
        g_topBox[r]  = b;
        g_topArea[r] = __fmul_rn(__fsub_rn(b.z, b.x), __fsub_rn(b.w, b.y));
    }
}

// --------- IoU decision: screened EXACT compare (fp32 FMA fast path) -------
// RN(inter/mu) > 0.7f  <=>  inter - 0.7f*mu >= 2^-25 * mu   (exact reals;
// 2^-25 = midpoint(0.7f, nextafterf(0.7f)) - 0.7f, a power of two => t exact).
// d = fmaf(-0.7f, mu, inter) has <=0.5ulp error RELATIVE TO d, so outside a
// +/-25% band around t the decision is provably identical; in-band falls back
// to the reference fdiv-then-compare.
__device__ __forceinline__ bool iou_gt(float4 a, float aa, float4 b, float ab) {
    float ty = fmaxf(a.x, b.x);
    float tx = fmaxf(a.y, b.y);
    float by = fminf(a.z, b.z);
    float bx = fminf(a.w, b.w);
    float hh = fmaxf(__fsub_rn(by, ty), 0.0f);
    float ww = fmaxf(__fsub_rn(bx, tx), 0.0f);
    float inter = __fmul_rn(hh, ww);
    float uni = __fsub_rn(__fadd_rn(aa, ab), inter);
    float mu  = fmaxf(uni, 1e-9f);
    float d = __fmaf_rn(-NMS_T, mu, inter);
    float t = __fmul_rn(2.9802322387695312e-8f, mu);   // 2^-25 * mu, exact
    if (d > __fmul_rn(1.25f, t)) return true;
    if (d < __fmul_rn(0.75f, t)) return false;
    return __fdiv_rn(inter, mu) > NMS_T;               // rare exact fallback
}

// ---- K4: stage-1 suppression mask: 2080 triangular blocks x 256 threads ---
// tile (rb, cb), cb <= rb; thread = (q = row-group 0..3, jj = column 0..63).
__global__ void __launch_bounds__(256) k_maskT() {
    int idx = blockIdx.x;
    // triangular index -> (rb, cb)
    int rb = (int)((sqrtf(8.0f * (float)idx + 1.0f) - 1.0f) * 0.5f);
    while ((rb + 1) * (rb + 2) / 2 <= idx) ++rb;
    while (rb * (rb + 1) / 2 > idx) --rb;
    int cb = idx - rb * (rb + 1) / 2;

    __shared__ float4 rB[64];
    __shared__ float  rA[64];
    __shared__ float4 cB[64];
    __shared__ float  cA[64];
    __shared__ ull    mP[4][64];

    int tid = threadIdx.x;
    int jj = tid & 63, q = tid >> 6;
    if (tid < 64)       { rB[tid] = g_topBox[rb * 64 + tid]; rA[tid] = g_topArea[rb * 64 + tid]; }
    else if (tid < 128) { int j = tid - 64; cB[j] = g_topBox[cb * 64 + j]; cA[j] = g_topArea[cb * 64 + j]; }
    __syncthreads();

    bool isDiag = (rb == cb);
    float4 cbox = cB[jj];
    float  ca   = cA[jj];

    // column word partial: rows [q*16, q*16+16)
    ull w = 0ull;
    int r0 = q * 16, r1 = r0 + 16;
    for (int r = r0; r < r1; r++) {
        if (isDiag && r <= jj) continue;
        if (iou_gt(cbox, ca, rB[r], rA[r])) w |= (1ull << r);
    }
    mP[q][jj] = w;
    __syncthreads();
    if (q == 0)
        g_maskT[(size_t)(cb * 64 + jj) * 64 + rb] =
            mP[0][jj] | mP[1][jj] | mP[2][jj] | mP[3][jj];

    if (isDiag) {   // row word: row jj vs columns j < jj, split across q
        __syncthreads();
        float4 rbox = rB[jj];
        float  ra = rA[jj];
        ull dw = 0ull;
        int j0 = q * 16, j1 = j0 + 16; if (j1 > jj) j1 = jj;
        for (int j = j0; j < j1; j++)
            if (iou_gt(rbox, ra, cB[j], cA[j])) dw |= (1ull << j);
        mP[q][jj] = dw;
        __syncthreads();
        if (q == 0)
            g_diag[rb * 64 + jj] = mP[0][jj] | mP[1][jj] | mP[2][jj] | mP[3][jj];
    }
}

// ------ K5: resolve (frontier greedy + MLP supB updates) + fused tail ------
__global__ void __launch_bounds__(512, 1) k_resolve(float* __restrict__ out) {
    __shared__ ull supB[64];
    __shared__ ull keptMask[64];
    __shared__ ull sDiag[2][64];
    __shared__ int keptList[64];
    __shared__ int sNK, sKept, sStop;
    __shared__ int wordBase[64];
    __shared__ float4 kb[NPOST];
    __shared__ float  ka[NPOST];
    __shared__ __align__(16) unsigned char uBuf[4096];   // supPart | tail scratch
    ull (*supPart)[64] = (ull (*)[64])uBuf;

    int tid = threadIdx.x, lane = tid & 31, warp = tid >> 5;   // 16 warps
    int vt = g_validTop;
    int end = (vt < B1) ? vt : B1;

    if (tid < 64) { supB[tid] = 0ull; keptMask[tid] = 0ull; }
    if (tid == 0) { sKept = 0; sNK = 0; sStop = (end <= 0) ? 1 : 0; }
    if (tid < 64) sDiag[0][tid] = (tid < end) ? __ldg(&g_diag[tid]) : 0ull;
    __syncthreads();

    if (!sStop) {
        int keptR = 0;
        int pb = 0;
        for (int base = 0; base < end; base += 64, pb ^= 1) {
            int cw = base >> 6;
            int cn = end - base; if (cn > 64) cn = 64;
            int nbase = base + 64;

            if (warp == 0) {
                ull sup = supB[cw];
                ull cand = ~sup;
                if (cn < 64) cand &= (1ull << cn) - 1ull;
                ull rowLo = sDiag[pb][lane];
                ull rowHi = sDiag[pb][lane + 32];
                ull U = cand, K = 0ull;
                while (U) {   // frontier rounds == sequential greedy
                    bool flo = ((U >> lane) & 1ull) && ((rowLo & U) == 0ull);
                    bool fhi = ((U >> (lane + 32)) & 1ull) && ((rowHi & U) == 0ull);
                    ull F = (ull)__ballot_sync(0xffffffffu, flo)
                          | ((ull)__ballot_sync(0xffffffffu, fhi) << 32);
                    K |= F;
                    bool qlo = (rowLo & F) != 0ull;
                    bool qhi = (rowHi & F) != 0ull;
                    ull S = (ull)__ballot_sync(0xffffffffu, qlo)
                          | ((ull)__ballot_sync(0xffffffffu, qhi) << 32);
                    U &= ~(F | S | K);
                }
                int c = __popcll(K);
                int room = NPOST - keptR;
                while (c > room) { K &= ~(1ull << (63 - __clzll(K))); c--; }
                keptR += c;
                bool bLo = (K >> lane) & 1ull;
                bool bHi = (K >> (lane + 32)) & 1ull;
                int pLo = __popcll(K & ((1ull << lane) - 1ull));
                int pHi = __popcll(K & ((1ull << (lane + 32)) - 1ull));
                if (bLo) keptList[pLo] = lane;
                if (bHi) keptList[pHi] = lane + 32;
                if (lane == 0) {
                    keptMask[cw] = K;
                    sNK = c;
                    sKept = keptR;
                    sStop = (keptR >= NPOST) ? 1 : 0;
                }
            } else if (warp == 1 && nbase < end) {
                sDiag[pb ^ 1][lane] =
                    (nbase + lane < end) ? __ldg(&g_diag[nbase + lane]) : 0ull;
                sDiag[pb ^ 1][lane + 32] =
                    (nbase + lane + 32 < end) ? __ldg(&g_diag[nbase + lane + 32]) : 0ull;
            }
            __syncthreads();

            int nK = sNK;
            if (sStop || nbase >= end) break;

            if (nK) {
                int g = tid >> 6, w = tid & 63;
                int lo = (nK * g) >> 3;
                int hi = (nK * (g + 1)) >> 3;
                ull a0 = 0ull, a1 = 0ull, a2 = 0ull, a3 = 0ull;
                int c2 = lo;
                for (; c2 + 4 <= hi; c2 += 4) {
                    a0 |= __ldg(&g_maskT[(size_t)(base + keptList[c2])     * 64 + w]);
                    a1 |= __ldg(&g_maskT[(size_t)(base + keptList[c2 + 1]) * 64 + w]);
                    a2 |= __ldg(&g_maskT[(size_t)(base + keptList[c2 + 2]) * 64 + w]);
                    a3 |= __ldg(&g_maskT[(size_t)(base + keptList[c2 + 3]) * 64 + w]);
                }
                for (; c2 < hi; c2++)
                    a0 |= __ldg(&g_maskT[(size_t)(base + keptList[c2]) * 64 + w]);
                supPart[g][w] = (a0 | a1) | (a2 | a3);
                __syncthreads();
                if (tid < 64)
                    supB[tid] |= supPart[0][tid] | supPart[1][tid] | supPart[2][tid]
                               | supPart[3][tid] | supPart[4][tid] | supPart[5][tid]
                               | supPart[6][tid] | supPart[7][tid];
                __syncthreads();
            }
        }
    }
    __syncthreads();

    int kept = sKept;

    // ---- epilogue: prefix popcounts + parallel output writes + zero fill --
    if (warp == 0) {
        int carry = 0;
        for (int g = 0; g < 64; g += 32) {
            int ww = g + lane;
            int v = __popcll(keptMask[ww]);
            int incl = v;
#pragma unroll
            for (int o = 1; o < 32; o <<= 1) {
                int t2 = __shfl_up_sync(0xffffffffu, incl, o);
                if (lane >= o) incl += t2;
            }
            wordBase[ww] = carry + incl - v;
            carry += __shfl_sync(0xffffffffu, incl, 31);
        }
    }
    __syncthreads();
    for (int p = tid; p < 64 * 64; p += 512) {
        int w = p >> 6, b = p & 63;
        ull km = keptMask[w];
        if ((km >> b) & 1ull) {
            int pos = wordBase[w] + __popcll(km & ((1ull << b) - 1ull));
            ((float4*)out)[pos] = g_topBox[w * 64 + b];
        }
    }
    for (int p = kept * 4 + tid; p < NPOST * 4; p += 512) out[p] = 0.0f;

    // ---- cleanup for next graph replay (self-cleaning pipeline) ----
    if (tid == 0) {
        g_candCount  = 0;
        g_decodeDone = 0;
        g_gatherDone = 0;
        g_binDone    = 0;
        g_kthKey     = 1u;
    }
    {
        int4* h = (int4*)g_hist1;
        for (int k = tid; k < 16384; k += 512) h[k] = make_int4(0, 0, 0, 0);
        int4* bc = (int4*)g_binCnt;
        for (int k = tid; k < BINS / 4; k += 512) bc[k] = make_int4(0, 0, 0, 0);
        int4* bf = (int4*)g_binFill;
        for (int k = tid; k < BINS / 4; k += 512) bf[k] = make_int4(0, 0, 0, 0);
    }
    __syncthreads();

    // ================= fused tail (rare): ranks >= B1 ======================
    if (kept >= NPOST || vt <= B1) return;

    float4* cb    = (float4*)(uBuf);            // 64 * 16 = 1024 B
    float*  caA   = (float*)(uBuf + 1024);      // 64 * 4  = 256 B
    ull*    lmask = (ull*)(uBuf + 1280);        // 64 * 8  = 512 B
    int*    supf  = (int*)(uBuf + 1792);        // 64 * 4  = 256 B
    __shared__ ull sKeepLocal;
    __shared__ int sKept2;

    for (int p = tid; p < 64 * 64; p += 512) {
        int w = p >> 6, b = p & 63;
        ull km = keptMask[w];
        if ((km >> b) & 1ull) {
            int pos = wordBase[w] + __popcll(km & ((1ull << b) - 1ull));
            kb[pos] = g_topBox[w * 64 + b];
            ka[pos] = g_topArea[w * 64 + b];
        }
    }
    __syncthreads();

    for (int base = B1; base < vt && kept < NPOST; base += 64) {
        int cn = vt - base; if (cn > 64) cn = 64;

        if (tid < 64) {
            supf[tid]  = 0;
            lmask[tid] = 0ull;
            if (tid < cn) {
                cb[tid]  = g_topBox[base + tid];
                caA[tid] = g_topArea[base + tid];
            }
        }
        __syncthreads();

        for (int i = warp; i < cn; i += 16) {
            float4 bi = cb[i];
            float  ai = caA[i];
            bool any = false;
            for (int j = lane; j < kept; j += 32)
                if (iou_gt(bi, ai, kb[j], ka[j])) { any = true; break; }
            bool w = __any_sync(0xffffffffu, any);
            if (w && lane == 0) supf[i] = 1;
        }
        for (int p = tid; p < 64 * 64; p += 512) {
            int i = p >> 6, j = p & 63;
            if (i < cn && j < i)
                if (iou_gt(cb[i], caA[i], cb[j], caA[j]))
                    atomicOr(&lmask[i], 1ull << j);
        }
        __syncthreads();

        if (tid == 0) {
            ull kl = 0ull;
            int kc = kept;
            for (int i = 0; i < cn && kc < NPOST; i++) {
                if (!supf[i] && !(lmask[i] & kl)) { kl |= 1ull << i; kc++; }
            }
            sKeepLocal = kl; sKept2 = kc;
        }
        __syncthreads();

        ull kl = sKeepLocal;
        if (tid < cn && ((kl >> tid) & 1ull)) {
            int pos = kept + __popcll(kl & ((1ull << tid) - 1ull));
            kb[pos] = cb[tid];
            ka[pos] = caA[tid];
            ((float4*)out)[pos] = cb[tid];
        }
        __syncthreads();
        kept = sKept2;
        __syncthreads();
    }
}

// ------------------------------- launcher ----------------------------------
extern "C" void kernel_launch(void* const* d_in, const int* in_sizes, int n_in,
                              void* d_out, int out_size) {
    const float* anchors = (const float*)d_in[0];
    const float* offsets = (const float*)d_in[1];
    const float* scores  = (const float*)d_in[2];
    const int*   ph      = (const int*)d_in[3];
    const int*   pw      = (const int*)d_in[4];
    const int*   ps      = (const int*)d_in[5];
    float* out = (float*)d_out;

    int n = in_sizes[2];
    if (n > NMAX) n = NMAX;

    k_decode<<<(n + 1023) / 1024, 1024>>>((const float4*)anchors,
                                          (const float4*)offsets,
                                          scores, ph, pw, ps, n);
    k_gather<<<(n + 255) / 256, 256>>>(n);
    k_binrank<<<CAP / 256, 256>>>();
    k_maskT<<<NTILES1, 256>>>();
    k_resolve<<<1, 512>>>(out);
}